// round 1
// baseline (speedup 1.0000x reference)
#include <cuda_runtime.h>

#define N_NODES 10000
#define N_EDGES 320000
#define KDIM 5
#define C_IN 128
#define C_OUT 128
#define KI 640  // KDIM * C_IN

// Scratch (static __device__ arrays are the sanctioned alloc-free workaround)
__device__ float g_res[(size_t)N_NODES * KI];   // 25.6 MB
__device__ int   g_rowptr[N_NODES + 1];

// ---------- packed f32x2 helpers (Blackwell FFMA2: 2x fp32 FMA rate) ----------
__device__ __forceinline__ unsigned long long pk2(float a, float b) {
    unsigned long long r;
    asm("mov.b64 %0, {%1, %2};" : "=l"(r) : "f"(a), "f"(b));
    return r;
}
__device__ __forceinline__ void unpk2(unsigned long long v, float &a, float &b) {
    asm("mov.b64 {%0, %1}, %2;" : "=f"(a), "=f"(b) : "l"(v));
}
__device__ __forceinline__ unsigned long long ffma2(unsigned long long a,
                                                    unsigned long long b,
                                                    unsigned long long c) {
    unsigned long long d;
    asm("fma.rn.f32x2 %0, %1, %2, %3;" : "=l"(d) : "l"(a), "l"(b), "l"(c));
    return d;
}

// ---------- int64-vs-int32 edge_index detection ----------
// If data is int64 (little endian, values < 2^31), every odd 32-bit word is 0.
// Probe 4 high words in the middle of the buffer; for int32 data those words are
// dst[1],dst[3],dst[5],dst[7] (all-zero prob ~1e-16).
__device__ __forceinline__ int detect_stride(const int* __restrict__ w) {
    bool is64 = (w[N_EDGES + 1] == 0) && (w[N_EDGES + 3] == 0) &&
                (w[N_EDGES + 5] == 0) && (w[N_EDGES + 7] == 0);
    return is64 ? 2 : 1;
}

// ---------- Kernel 1: CSR rowptr via binary search (src is sorted) ----------
__global__ void build_rowptr_kernel(const int* __restrict__ ei) {
    int n = blockIdx.x * blockDim.x + threadIdx.x;
    if (n > N_NODES) return;
    int stride = detect_stride(ei);
    int lo = 0, hi = N_EDGES;
    while (lo < hi) {
        int mid = (lo + hi) >> 1;
        int s = ei[(size_t)mid * stride];  // low word = value
        if (s < n) lo = mid + 1; else hi = mid;
    }
    g_rowptr[n] = lo;
}

// ---------- Kernel 2: per-node edge accumulation (warp per node, no atomics) ----
// res[n, k*128 + i] = sum_{e in node n} X[e,k] * h[dst[e], i]
__global__ void edge_accum_kernel(const float* __restrict__ h,
                                  const float* __restrict__ X,
                                  const int* __restrict__ ei) {
    int gwarp = (blockIdx.x * blockDim.x + threadIdx.x) >> 5;
    int lane  = threadIdx.x & 31;
    if (gwarp >= N_NODES) return;

    int stride = detect_stride(ei);
    const int* dstp = ei + (size_t)N_EDGES * stride;

    int start = g_rowptr[gwarp];
    int end   = g_rowptr[gwarp + 1];

    unsigned long long acc[KDIM][2];
#pragma unroll
    for (int k = 0; k < KDIM; k++) { acc[k][0] = 0ull; acc[k][1] = 0ull; }

    const float* hb = h + lane * 4;  // each lane owns 4 channels
    for (int e = start; e < end; e++) {
        int d = dstp[(size_t)e * stride];
        float4 hv = *(const float4*)(hb + (size_t)d * C_IN);
        unsigned long long h01 = pk2(hv.x, hv.y);
        unsigned long long h23 = pk2(hv.z, hv.w);
        const float* xp = X + (size_t)e * KDIM;
#pragma unroll
        for (int k = 0; k < KDIM; k++) {
            float xk = __ldg(xp + k);
            unsigned long long x2 = pk2(xk, xk);
            acc[k][0] = ffma2(x2, h01, acc[k][0]);
            acc[k][1] = ffma2(x2, h23, acc[k][1]);
        }
    }

    float* r = g_res + (size_t)gwarp * KI + lane * 4;
#pragma unroll
    for (int k = 0; k < KDIM; k++) {
        float4 v;
        unpk2(acc[k][0], v.x, v.y);
        unpk2(acc[k][1], v.z, v.w);
        *(float4*)(r + k * C_IN) = v;
    }
}

// ---------- Kernel 3: out(10000x128) = res(10000x640) @ W(640x128) + bias ------
#define BM 32
#define BN 64
#define BK 16
#define APITCH 34  // u64 units; even pitch keeps 16B alignment, breaks conflicts

__global__ void gemm_bias_kernel(const float* __restrict__ W,
                                 const float* __restrict__ bias,
                                 float* __restrict__ out) {
    __shared__ __align__(16) unsigned long long A2[BK * APITCH];  // A duplicated {a,a} pairs
    __shared__ __align__(16) float Bs[BK * BN];

    int tid = threadIdx.x;   // 128 threads
    int tx = tid & 15;       // col group (4 cols)
    int ty = tid >> 4;       // row group (4 rows)
    int m0 = blockIdx.x * BM;
    int n0 = blockIdx.y * BN;

    unsigned long long acc[4][2];
#pragma unroll
    for (int m = 0; m < 4; m++) { acc[m][0] = 0ull; acc[m][1] = 0ull; }

    for (int k0 = 0; k0 < KI; k0 += BK) {
        // stage A (32 rows x 16 k), duplicated into 64-bit pairs for FFMA2
        {
            int lc = tid & 15;   // kk
            int lm = tid >> 4;   // m base
#pragma unroll
            for (int j = 0; j < 4; j++) {
                int m = lm + j * 8;
                int row = m0 + m;
                float v = (row < N_NODES) ? g_res[(size_t)row * KI + k0 + lc] : 0.0f;
                A2[lc * APITCH + m] = pk2(v, v);
            }
        }
        // stage B (16 k x 64 cols)
#pragma unroll
        for (int j = 0; j < 2; j++) {
            int kk = (tid >> 4) + j * 8;
            int n  = (tid & 15) * 4;
            float4 w = *(const float4*)(W + (size_t)(k0 + kk) * C_OUT + n0 + n);
            *(float4*)(Bs + kk * BN + n) = w;
        }
        __syncthreads();

#pragma unroll
        for (int kk = 0; kk < BK; kk++) {
            ulonglong2 a01 = *(const ulonglong2*)(A2 + kk * APITCH + ty * 4);
            ulonglong2 a23 = *(const ulonglong2*)(A2 + kk * APITCH + ty * 4 + 2);
            ulonglong2 b   = *(const ulonglong2*)(Bs + kk * BN + tx * 4);
            acc[0][0] = ffma2(a01.x, b.x, acc[0][0]);
            acc[0][1] = ffma2(a01.x, b.y, acc[0][1]);
            acc[1][0] = ffma2(a01.y, b.x, acc[1][0]);
            acc[1][1] = ffma2(a01.y, b.y, acc[1][1]);
            acc[2][0] = ffma2(a23.x, b.x, acc[2][0]);
            acc[2][1] = ffma2(a23.x, b.y, acc[2][1]);
            acc[3][0] = ffma2(a23.y, b.x, acc[3][0]);
            acc[3][1] = ffma2(a23.y, b.y, acc[3][1]);
        }
        __syncthreads();
    }

    float4 bv = *(const float4*)(bias + n0 + tx * 4);
#pragma unroll
    for (int m = 0; m < 4; m++) {
        int row = m0 + ty * 4 + m;
        if (row < N_NODES) {
            float4 o;
            unpk2(acc[m][0], o.x, o.y);
            unpk2(acc[m][1], o.z, o.w);
            o.x += bv.x; o.y += bv.y; o.z += bv.z; o.w += bv.w;
            *(float4*)(out + (size_t)row * C_OUT + n0 + tx * 4) = o;
        }
    }
}

extern "C" void kernel_launch(void* const* d_in, const int* in_sizes, int n_in,
                              void* d_out, int out_size) {
    const float* h    = (const float*)d_in[0];
    const float* X    = (const float*)d_in[1];
    const int*   ei   = (const int*)d_in[2];   // int32 or int64, detected on device
    // d_in[3] = batch_node (unused by reference math)
    const float* W    = (const float*)d_in[4];
    const float* bias = (const float*)d_in[5];
    float* out = (float*)d_out;

    build_rowptr_kernel<<<(N_NODES + 256) / 256, 256>>>(ei);
    edge_accum_kernel<<<(N_NODES * 32 + 255) / 256, 256>>>(h, X, ei);
    gemm_bias_kernel<<<dim3((N_NODES + BM - 1) / BM, C_OUT / BN), 128>>>(W, bias, out);
}

// round 3
// speedup vs baseline: 1.5364x; 1.5364x over previous
#include <cuda_runtime.h>
#include <cuda_bf16.h>
#include <cstdint>

#define N_NODES 10000
#define N_EDGES 320000
#define KDIM 5
#define C_IN 128
#define C_OUT 128
#define KI 640            // KDIM * C_IN
#define M_PAD 10112       // 79 * 128 (zero pad rows stay zero forever)

// ---------------- device scratch (alloc-free) ----------------
__device__ __nv_bfloat16 g_Ahi[(size_t)M_PAD * KI];
__device__ __nv_bfloat16 g_Alo[(size_t)M_PAD * KI];
__device__ __nv_bfloat16 g_Bhi[(size_t)C_OUT * KI];   // [o][ki] K-major (= B col-major)
__device__ __nv_bfloat16 g_Blo[(size_t)C_OUT * KI];
__device__ int g_rowptr[N_NODES + 1];

// ---------------- helpers ----------------
__device__ __forceinline__ unsigned long long pk2(float a, float b) {
    unsigned long long r;
    asm("mov.b64 %0, {%1, %2};" : "=l"(r) : "f"(a), "f"(b));
    return r;
}
__device__ __forceinline__ unsigned long long ffma2(unsigned long long a,
                                                    unsigned long long b,
                                                    unsigned long long c) {
    unsigned long long d;
    asm("fma.rn.f32x2 %0, %1, %2, %3;" : "=l"(d) : "l"(a), "l"(b), "l"(c));
    return d;
}
__device__ __forceinline__ void unpk2(unsigned long long v, float &a, float &b) {
    asm("mov.b64 {%0, %1}, %2;" : "=f"(a), "=f"(b) : "l"(v));
}
__device__ __forceinline__ int detect_stride(const int* __restrict__ w) {
    bool is64 = (w[N_EDGES + 1] == 0) && (w[N_EDGES + 3] == 0) &&
                (w[N_EDGES + 5] == 0) && (w[N_EDGES + 7] == 0);
    return is64 ? 2 : 1;
}
__device__ __forceinline__ uint32_t su32(const void* p) {
    return (uint32_t)__cvta_generic_to_shared(p);
}
__device__ __forceinline__ void cp16(uint32_t dst, const void* src) {
    asm volatile("cp.async.cg.shared.global [%0], [%1], 16;" :: "r"(dst), "l"(src) : "memory");
}
__device__ __forceinline__ void cp_commit() {
    asm volatile("cp.async.commit_group;" ::: "memory");
}
template <int N>
__device__ __forceinline__ void cp_wait() {
    asm volatile("cp.async.wait_group %0;" :: "n"(N) : "memory");
}
// mma.sync bf16: D(f32) += A(bf16) * B(bf16), m16n8k16, A row-major, B col-major
__device__ __forceinline__ void mma16816(float* d, const uint32_t* a, const uint32_t* b) {
    asm volatile(
        "mma.sync.aligned.m16n8k16.row.col.f32.bf16.bf16.f32 "
        "{%0,%1,%2,%3}, {%4,%5,%6,%7}, {%8,%9}, {%0,%1,%2,%3};"
        : "+f"(d[0]), "+f"(d[1]), "+f"(d[2]), "+f"(d[3])
        : "r"(a[0]), "r"(a[1]), "r"(a[2]), "r"(a[3]), "r"(b[0]), "r"(b[1]));
}

// ---------------- Kernel 1: prep = W split-transpose + rowptr scatter ----------
#define WT_BLOCKS 80   // (640/32) * (128/32)
__global__ void prep_kernel(const int* __restrict__ ei, const float* __restrict__ W) {
    if (blockIdx.x < WT_BLOCKS) {
        __shared__ float tile[32][33];
        int bki = blockIdx.x >> 2;        // 0..19  (ki block)
        int bo  = blockIdx.x & 3;         // 0..3   (o block)
        int tx = threadIdx.x & 31;
        int ty = threadIdx.x >> 5;        // 0..7
#pragma unroll
        for (int j = 0; j < 4; j++) {
            int ki = bki * 32 + ty + j * 8;
            tile[ty + j * 8][tx] = W[(size_t)ki * C_OUT + bo * 32 + tx];
        }
        __syncthreads();
#pragma unroll
        for (int j = 0; j < 4; j++) {
            int o  = bo * 32 + ty + j * 8;
            int ki = bki * 32 + tx;
            float w = tile[tx][ty + j * 8];
            __nv_bfloat16 hi = __float2bfloat16(w);
            float lof = w - __bfloat162float(hi);
            g_Bhi[(size_t)o * KI + ki] = hi;
            g_Blo[(size_t)o * KI + ki] = __float2bfloat16(lof);
        }
    } else {
        int e = (blockIdx.x - WT_BLOCKS) * 256 + threadIdx.x;
        if (e <= N_EDGES) {
            int stride = detect_stride(ei);
            int s_cur  = (e < N_EDGES) ? ei[(size_t)e * stride] : N_NODES;
            int s_prev = (e == 0) ? -1 : ei[(size_t)(e - 1) * stride];
            for (int n = s_prev + 1; n <= s_cur; n++) g_rowptr[n] = e;
        }
    }
}

// ---------------- Kernel 2: per-node edge accumulation (warp per node) ---------
__global__ void edge_accum_kernel(const float* __restrict__ h,
                                  const float* __restrict__ X,
                                  const int* __restrict__ ei) {
    int gwarp = (blockIdx.x * blockDim.x + threadIdx.x) >> 5;
    int lane  = threadIdx.x & 31;
    if (gwarp >= N_NODES) return;

    int stride = detect_stride(ei);
    const int* dstp = ei + (size_t)N_EDGES * stride;

    int start = g_rowptr[gwarp];
    int end   = g_rowptr[gwarp + 1];

    unsigned long long acc[KDIM][2];
#pragma unroll
    for (int k = 0; k < KDIM; k++) { acc[k][0] = 0ull; acc[k][1] = 0ull; }

    const float* hb = h + lane * 4;
    int e = start;
    int cnt = end - start;
    int n2 = start + (cnt & ~1);
    for (; e < n2; e += 2) {
        int d0 = dstp[(size_t)e * stride];
        int d1 = dstp[(size_t)(e + 1) * stride];
        float4 hv0 = *(const float4*)(hb + (size_t)d0 * C_IN);
        float4 hv1 = *(const float4*)(hb + (size_t)d1 * C_IN);
        const float* xp0 = X + (size_t)e * KDIM;
        const float* xp1 = xp0 + KDIM;
        float x0[KDIM], x1[KDIM];
#pragma unroll
        for (int k = 0; k < KDIM; k++) { x0[k] = __ldg(xp0 + k); x1[k] = __ldg(xp1 + k); }
        unsigned long long h001 = pk2(hv0.x, hv0.y), h023 = pk2(hv0.z, hv0.w);
        unsigned long long h101 = pk2(hv1.x, hv1.y), h123 = pk2(hv1.z, hv1.w);
#pragma unroll
        for (int k = 0; k < KDIM; k++) {
            unsigned long long xa = pk2(x0[k], x0[k]);
            unsigned long long xb = pk2(x1[k], x1[k]);
            acc[k][0] = ffma2(xa, h001, acc[k][0]);
            acc[k][1] = ffma2(xa, h023, acc[k][1]);
            acc[k][0] = ffma2(xb, h101, acc[k][0]);
            acc[k][1] = ffma2(xb, h123, acc[k][1]);
        }
    }
    if (e < end) {
        int d = dstp[(size_t)e * stride];
        float4 hv = *(const float4*)(hb + (size_t)d * C_IN);
        unsigned long long h01 = pk2(hv.x, hv.y), h23 = pk2(hv.z, hv.w);
        const float* xp = X + (size_t)e * KDIM;
#pragma unroll
        for (int k = 0; k < KDIM; k++) {
            float xk = __ldg(xp + k);
            unsigned long long x2 = pk2(xk, xk);
            acc[k][0] = ffma2(x2, h01, acc[k][0]);
            acc[k][1] = ffma2(x2, h23, acc[k][1]);
        }
    }

    // emit bf16 hi/lo pairs
#pragma unroll
    for (int k = 0; k < KDIM; k++) {
        float4 v;
        unpk2(acc[k][0], v.x, v.y);
        unpk2(acc[k][1], v.z, v.w);
        size_t idx = (size_t)gwarp * KI + k * C_IN + lane * 4;
        __nv_bfloat162 h01 = __float22bfloat162_rn(make_float2(v.x, v.y));
        __nv_bfloat162 h23 = __float22bfloat162_rn(make_float2(v.z, v.w));
        float l0 = v.x - __bfloat162float(h01.x);
        float l1 = v.y - __bfloat162float(h01.y);
        float l2 = v.z - __bfloat162float(h23.x);
        float l3 = v.w - __bfloat162float(h23.y);
        __nv_bfloat162 lo01 = __float22bfloat162_rn(make_float2(l0, l1));
        __nv_bfloat162 lo23 = __float22bfloat162_rn(make_float2(l2, l3));
        uint2 hs, ls;
        hs.x = *(uint32_t*)&h01; hs.y = *(uint32_t*)&h23;
        ls.x = *(uint32_t*)&lo01; ls.y = *(uint32_t*)&lo23;
        *(uint2*)(&g_Ahi[idx]) = hs;
        *(uint2*)(&g_Alo[idx]) = ls;
    }
}

// ---------------- Kernel 3: HMMA bf16-split GEMM -------------------------------
// out(10000x128) = Ahi@Bhi^T + Ahi@Blo^T + Alo@Bhi^T + bias
#define GBM 128
#define GBN 128
#define GBK 32
#define NSTAGE 20            // KI / GBK
#define APITCH 40            // bf16 per row (80 B): (20n+tg) mod 32 distinct -> conflict-free
#define TILE_B (128 * APITCH * 2)        // 10240 B per tile
#define STAGE_B (4 * TILE_B)             // 40960 B
#define GSMEM (2 * STAGE_B)              // 81920 B

__device__ __forceinline__ uint32_t lds32(const __nv_bfloat16* base, int row, int kcol) {
    return *(const uint32_t*)(base + row * APITCH + kcol);
}

__global__ void __launch_bounds__(256, 1)
gemm_hmma_kernel(const float* __restrict__ bias, float* __restrict__ out) {
    extern __shared__ __align__(16) char smem[];
    __shared__ float sbias[C_OUT];

    int tid = threadIdx.x;
    int lane = tid & 31, wid = tid >> 5;
    int g = lane >> 2, tg = lane & 3;
    int m0 = blockIdx.x * GBM;
    int wm0 = (wid & 1) * 64;       // warp tile 64 x 32
    int wn0 = (wid >> 1) * 32;

    if (tid < C_OUT) sbias[tid] = bias[tid];

    // stage loader: 4 tiles x 512 16B-words, 8 cp16 per thread
    auto load_stage = [&](int i) {
        int k0 = i * GBK;
        char* sbuf = smem + (i & 1) * STAGE_B;
        const __nv_bfloat16* srcs[4] = {
            g_Ahi + (size_t)m0 * KI + k0,
            g_Alo + (size_t)m0 * KI + k0,
            g_Bhi + k0,
            g_Blo + k0 };
#pragma unroll
        for (int t = 0; t < 4; t++) {
            uint32_t dbase = su32(sbuf + t * TILE_B);
            const __nv_bfloat16* src = srcs[t];
#pragma unroll
            for (int j = 0; j < 2; j++) {
                int w = tid + j * 256;          // 0..511
                int r = w >> 2, c = w & 3;
                cp16(dbase + (uint32_t)(r * (APITCH * 2) + c * 16),
                     src + (size_t)r * KI + c * 8);
            }
        }
        cp_commit();
    };

    float acc[4][4][4];
#pragma unroll
    for (int mt = 0; mt < 4; mt++)
#pragma unroll
        for (int nt = 0; nt < 4; nt++)
#pragma unroll
            for (int j = 0; j < 4; j++) acc[mt][nt][j] = 0.0f;

    load_stage(0);

    for (int i = 0; i < NSTAGE; i++) {
        if (i + 1 < NSTAGE) { load_stage(i + 1); cp_wait<1>(); }
        else                { cp_wait<0>(); }
        __syncthreads();

        const char* sbuf = smem + (i & 1) * STAGE_B;
        const __nv_bfloat16* sAhi = (const __nv_bfloat16*)(sbuf);
        const __nv_bfloat16* sAlo = (const __nv_bfloat16*)(sbuf + TILE_B);
        const __nv_bfloat16* sBhi = (const __nv_bfloat16*)(sbuf + 2 * TILE_B);
        const __nv_bfloat16* sBlo = (const __nv_bfloat16*)(sbuf + 3 * TILE_B);

#pragma unroll
        for (int kk = 0; kk < GBK; kk += 16) {
            uint32_t ahi[4][4], alo[4][4], bhi[4][2], blo[4][2];
#pragma unroll
            for (int mt = 0; mt < 4; mt++) {
                int r = wm0 + mt * 16 + g;
                int kc = kk + tg * 2;
                ahi[mt][0] = lds32(sAhi, r,     kc);
                ahi[mt][1] = lds32(sAhi, r + 8, kc);
                ahi[mt][2] = lds32(sAhi, r,     kc + 8);
                ahi[mt][3] = lds32(sAhi, r + 8, kc + 8);
                alo[mt][0] = lds32(sAlo, r,     kc);
                alo[mt][1] = lds32(sAlo, r + 8, kc);
                alo[mt][2] = lds32(sAlo, r,     kc + 8);
                alo[mt][3] = lds32(sAlo, r + 8, kc + 8);
            }
#pragma unroll
            for (int nt = 0; nt < 4; nt++) {
                int rn = wn0 + nt * 8 + g;
                int kc = kk + tg * 2;
                bhi[nt][0] = lds32(sBhi, rn, kc);
                bhi[nt][1] = lds32(sBhi, rn, kc + 8);
                blo[nt][0] = lds32(sBlo, rn, kc);
                blo[nt][1] = lds32(sBlo, rn, kc + 8);
            }
#pragma unroll
            for (int mt = 0; mt < 4; mt++)
#pragma unroll
                for (int nt = 0; nt < 4; nt++) {
                    mma16816(acc[mt][nt], ahi[mt], bhi[nt]);
                    mma16816(acc[mt][nt], ahi[mt], blo[nt]);
                    mma16816(acc[mt][nt], alo[mt], bhi[nt]);
                }
        }
        __syncthreads();
    }

    // epilogue
#pragma unroll
    for (int mt = 0; mt < 4; mt++) {
#pragma unroll
        for (int nt = 0; nt < 4; nt++) {
            int row = m0 + wm0 + mt * 16 + g;
            int col = wn0 + nt * 8 + tg * 2;
            float b0 = sbias[col], b1 = sbias[col + 1];
            if (row < N_NODES) {
                float2 o0 = make_float2(acc[mt][nt][0] + b0, acc[mt][nt][1] + b1);
                *(float2*)(out + (size_t)row * C_OUT + col) = o0;
            }
            if (row + 8 < N_NODES) {
                float2 o1 = make_float2(acc[mt][nt][2] + b0, acc[mt][nt][3] + b1);
                *(float2*)(out + (size_t)(row + 8) * C_OUT + col) = o1;
            }
        }
    }
}

// ---------------- host launch ----------------
extern "C" void kernel_launch(void* const* d_in, const int* in_sizes, int n_in,
                              void* d_out, int out_size) {
    const float* h    = (const float*)d_in[0];
    const float* X    = (const float*)d_in[1];
    const int*   ei   = (const int*)d_in[2];
    const float* W    = (const float*)d_in[4];
    const float* bias = (const float*)d_in[5];
    float* out = (float*)d_out;

    int rp_blocks = (N_EDGES + 1 + 255) / 256;   // 1251
    prep_kernel<<<WT_BLOCKS + rp_blocks, 256>>>(ei, W);
    edge_accum_kernel<<<(N_NODES * 32 + 255) / 256, 256>>>(h, X, ei);
    cudaFuncSetAttribute(gemm_hmma_kernel,
                         cudaFuncAttributeMaxDynamicSharedMemorySize, GSMEM);
    gemm_hmma_kernel<<<M_PAD / GBM, 256, GSMEM>>>(bias, out);
}

// round 4
// speedup vs baseline: 1.7249x; 1.1227x over previous
#include <cuda_runtime.h>
#include <cuda_bf16.h>
#include <cstdint>

#define N_NODES 10000
#define N_EDGES 320000
#define KDIM 5
#define C_IN 128
#define C_OUT 128
#define KI 640            // KDIM * C_IN
#define M_PAD 10112       // 158 * 64 (zero pad rows stay zero forever)

// ---------------- device scratch (alloc-free) ----------------
__device__ __nv_bfloat16 g_Ahi[(size_t)M_PAD * KI];
__device__ __nv_bfloat16 g_Alo[(size_t)M_PAD * KI];
__device__ __nv_bfloat16 g_Bhi[(size_t)C_OUT * KI];   // [o][ki] K-major (= B col-major)
__device__ __nv_bfloat16 g_Blo[(size_t)C_OUT * KI];
__device__ int g_rowptr[N_NODES + 1];

// ---------------- helpers ----------------
__device__ __forceinline__ unsigned long long pk2(float a, float b) {
    unsigned long long r;
    asm("mov.b64 %0, {%1, %2};" : "=l"(r) : "f"(a), "f"(b));
    return r;
}
__device__ __forceinline__ unsigned long long ffma2(unsigned long long a,
                                                    unsigned long long b,
                                                    unsigned long long c) {
    unsigned long long d;
    asm("fma.rn.f32x2 %0, %1, %2, %3;" : "=l"(d) : "l"(a), "l"(b), "l"(c));
    return d;
}
__device__ __forceinline__ void unpk2(unsigned long long v, float &a, float &b) {
    asm("mov.b64 {%0, %1}, %2;" : "=f"(a), "=f"(b) : "l"(v));
}
__device__ __forceinline__ int detect_stride(const int* __restrict__ w) {
    bool is64 = (w[N_EDGES + 1] == 0) && (w[N_EDGES + 3] == 0) &&
                (w[N_EDGES + 5] == 0) && (w[N_EDGES + 7] == 0);
    return is64 ? 2 : 1;
}
__device__ __forceinline__ uint32_t su32(const void* p) {
    return (uint32_t)__cvta_generic_to_shared(p);
}
__device__ __forceinline__ void cp16(uint32_t dst, const void* src) {
    asm volatile("cp.async.cg.shared.global [%0], [%1], 16;" :: "r"(dst), "l"(src) : "memory");
}
__device__ __forceinline__ void cp_commit() {
    asm volatile("cp.async.commit_group;" ::: "memory");
}
template <int N>
__device__ __forceinline__ void cp_wait() {
    asm volatile("cp.async.wait_group %0;" :: "n"(N) : "memory");
}
// mma.sync bf16: D(f32) += A(bf16) * B(bf16), m16n8k16, A row-major, B col-major
__device__ __forceinline__ void mma16816(float* d, const uint32_t* a, const uint32_t* b) {
    asm volatile(
        "mma.sync.aligned.m16n8k16.row.col.f32.bf16.bf16.f32 "
        "{%0,%1,%2,%3}, {%4,%5,%6,%7}, {%8,%9}, {%0,%1,%2,%3};"
        : "+f"(d[0]), "+f"(d[1]), "+f"(d[2]), "+f"(d[3])
        : "r"(a[0]), "r"(a[1]), "r"(a[2]), "r"(a[3]), "r"(b[0]), "r"(b[1]));
}

// ---------------- Kernel 1: prep = W split-transpose + rowptr scatter ----------
#define WT_BLOCKS 80   // (640/32) * (128/32)
__global__ void prep_kernel(const int* __restrict__ ei, const float* __restrict__ W) {
    if (blockIdx.x < WT_BLOCKS) {
        __shared__ float tile[32][33];
        int bki = blockIdx.x >> 2;        // 0..19  (ki block)
        int bo  = blockIdx.x & 3;         // 0..3   (o block)
        int tx = threadIdx.x & 31;
        int ty = threadIdx.x >> 5;        // 0..7
#pragma unroll
        for (int j = 0; j < 4; j++) {
            int ki = bki * 32 + ty + j * 8;
            tile[ty + j * 8][tx] = W[(size_t)ki * C_OUT + bo * 32 + tx];
        }
        __syncthreads();
#pragma unroll
        for (int j = 0; j < 4; j++) {
            int o  = bo * 32 + ty + j * 8;
            int ki = bki * 32 + tx;
            float w = tile[tx][ty + j * 8];
            __nv_bfloat16 hi = __float2bfloat16(w);
            float lof = w - __bfloat162float(hi);
            g_Bhi[(size_t)o * KI + ki] = hi;
            g_Blo[(size_t)o * KI + ki] = __float2bfloat16(lof);
        }
    } else {
        int e = (blockIdx.x - WT_BLOCKS) * 256 + threadIdx.x;
        if (e <= N_EDGES) {
            int stride = detect_stride(ei);
            int s_cur  = (e < N_EDGES) ? ei[(size_t)e * stride] : N_NODES;
            int s_prev = (e == 0) ? -1 : ei[(size_t)(e - 1) * stride];
            for (int n = s_prev + 1; n <= s_cur; n++) g_rowptr[n] = e;
        }
    }
}

// ---------------- Kernel 2: per-node edge accumulation (warp per node) ---------
__global__ void __launch_bounds__(256)
edge_accum_kernel(const float* __restrict__ h,
                  const float* __restrict__ X,
                  const int* __restrict__ ei) {
    int gwarp = (blockIdx.x * blockDim.x + threadIdx.x) >> 5;
    int lane  = threadIdx.x & 31;
    if (gwarp >= N_NODES) return;

    int stride = detect_stride(ei);
    const int* dstp = ei + (size_t)N_EDGES * stride;

    int start = g_rowptr[gwarp];
    int end   = g_rowptr[gwarp + 1];

    unsigned long long acc[KDIM][2];
#pragma unroll
    for (int k = 0; k < KDIM; k++) { acc[k][0] = 0ull; acc[k][1] = 0ull; }

    const float* hb = h + lane * 4;
    int e = start;

    // unroll-4: batch independent dst + X loads, then h loads, then FMA
    for (; e + 4 <= end; e += 4) {
        int d[4];
#pragma unroll
        for (int j = 0; j < 4; j++) d[j] = dstp[(size_t)(e + j) * stride];
        float x[4][KDIM];
#pragma unroll
        for (int j = 0; j < 4; j++) {
            const float* xp = X + (size_t)(e + j) * KDIM;
#pragma unroll
            for (int k = 0; k < KDIM; k++) x[j][k] = __ldg(xp + k);
        }
        float4 hv[4];
#pragma unroll
        for (int j = 0; j < 4; j++)
            hv[j] = *(const float4*)(hb + (size_t)d[j] * C_IN);
#pragma unroll
        for (int j = 0; j < 4; j++) {
            unsigned long long h01 = pk2(hv[j].x, hv[j].y);
            unsigned long long h23 = pk2(hv[j].z, hv[j].w);
#pragma unroll
            for (int k = 0; k < KDIM; k++) {
                unsigned long long x2 = pk2(x[j][k], x[j][k]);
                acc[k][0] = ffma2(x2, h01, acc[k][0]);
                acc[k][1] = ffma2(x2, h23, acc[k][1]);
            }
        }
    }
    for (; e < end; e++) {
        int d = dstp[(size_t)e * stride];
        float4 hv = *(const float4*)(hb + (size_t)d * C_IN);
        unsigned long long h01 = pk2(hv.x, hv.y), h23 = pk2(hv.z, hv.w);
        const float* xp = X + (size_t)e * KDIM;
#pragma unroll
        for (int k = 0; k < KDIM; k++) {
            float xk = __ldg(xp + k);
            unsigned long long x2 = pk2(xk, xk);
            acc[k][0] = ffma2(x2, h01, acc[k][0]);
            acc[k][1] = ffma2(x2, h23, acc[k][1]);
        }
    }

    // emit bf16 hi/lo pairs
#pragma unroll
    for (int k = 0; k < KDIM; k++) {
        float4 v;
        unpk2(acc[k][0], v.x, v.y);
        unpk2(acc[k][1], v.z, v.w);
        size_t idx = (size_t)gwarp * KI + k * C_IN + lane * 4;
        __nv_bfloat162 h01 = __float22bfloat162_rn(make_float2(v.x, v.y));
        __nv_bfloat162 h23 = __float22bfloat162_rn(make_float2(v.z, v.w));
        float l0 = v.x - __bfloat162float(h01.x);
        float l1 = v.y - __bfloat162float(h01.y);
        float l2 = v.z - __bfloat162float(h23.x);
        float l3 = v.w - __bfloat162float(h23.y);
        __nv_bfloat162 lo01 = __float22bfloat162_rn(make_float2(l0, l1));
        __nv_bfloat162 lo23 = __float22bfloat162_rn(make_float2(l2, l3));
        uint2 hs, ls;
        hs.x = *(uint32_t*)&h01; hs.y = *(uint32_t*)&h23;
        ls.x = *(uint32_t*)&lo01; ls.y = *(uint32_t*)&lo23;
        *(uint2*)(&g_Ahi[idx]) = hs;
        *(uint2*)(&g_Alo[idx]) = ls;
    }
}

// ---------------- Kernel 3: HMMA bf16-split GEMM, 64x64 tiles, 316 CTAs --------
// out(10000x128) = Ahi@Bhi^T + Ahi@Blo^T + Alo@Bhi^T + bias
#define GBM 64
#define GBN 64
#define GBK 32
#define NSTAGE 20            // KI / GBK
#define APITCH 40            // bf16 per row (80 B): (20g+tg) mod 32 distinct -> conflict-free
#define TILE_B (64 * APITCH * 2)         // 5120 B per tile
#define STAGE_B (4 * TILE_B)             // 20480 B
#define GSMEM (3 * STAGE_B)              // 61440 B (3-stage pipeline)

__device__ __forceinline__ uint32_t lds32(const __nv_bfloat16* base, int row, int kcol) {
    return *(const uint32_t*)(base + row * APITCH + kcol);
}

__global__ void __launch_bounds__(128, 2)
gemm_hmma_kernel(const float* __restrict__ bias, float* __restrict__ out) {
    extern __shared__ __align__(16) char smem[];
    __shared__ float sbias[GBN];

    int tid = threadIdx.x;
    int lane = tid & 31, wid = tid >> 5;
    int g = lane >> 2, tg = lane & 3;
    int m0 = blockIdx.x * GBM;
    int n0 = blockIdx.y * GBN;
    int wm0 = (wid & 1) * 32;       // warp tile 32 x 32
    int wn0 = (wid >> 1) * 32;

    if (tid < GBN) sbias[tid] = bias[n0 + tid];

    // stage loader: 4 tiles x 256 16B-words, 2 cp16 per thread per tile
    auto load_stage = [&](int i) {
        int k0 = i * GBK;
        char* sbuf = smem + (i % 3) * STAGE_B;
        const __nv_bfloat16* srcs[4] = {
            g_Ahi + (size_t)m0 * KI + k0,
            g_Alo + (size_t)m0 * KI + k0,
            g_Bhi + (size_t)n0 * KI + k0,
            g_Blo + (size_t)n0 * KI + k0 };
#pragma unroll
        for (int t = 0; t < 4; t++) {
            uint32_t dbase = su32(sbuf + t * TILE_B);
            const __nv_bfloat16* src = srcs[t];
#pragma unroll
            for (int j = 0; j < 2; j++) {
                int w = tid + j * 128;          // 0..255
                int r = w >> 2, c = w & 3;
                cp16(dbase + (uint32_t)(r * (APITCH * 2) + c * 16),
                     src + (size_t)r * KI + c * 8);
            }
        }
        cp_commit();
    };

    float acc[2][4][4];
#pragma unroll
    for (int mt = 0; mt < 2; mt++)
#pragma unroll
        for (int nt = 0; nt < 4; nt++)
#pragma unroll
            for (int j = 0; j < 4; j++) acc[mt][nt][j] = 0.0f;

    load_stage(0);
    load_stage(1);

    for (int i = 0; i < NSTAGE; i++) {
        if (i + 2 < NSTAGE)      { load_stage(i + 2); cp_wait<2>(); }
        else if (i + 1 < NSTAGE) { cp_wait<1>(); }
        else                     { cp_wait<0>(); }
        __syncthreads();

        const char* sbuf = smem + (i % 3) * STAGE_B;
        const __nv_bfloat16* sAhi = (const __nv_bfloat16*)(sbuf);
        const __nv_bfloat16* sAlo = (const __nv_bfloat16*)(sbuf + TILE_B);
        const __nv_bfloat16* sBhi = (const __nv_bfloat16*)(sbuf + 2 * TILE_B);
        const __nv_bfloat16* sBlo = (const __nv_bfloat16*)(sbuf + 3 * TILE_B);

#pragma unroll
        for (int kk = 0; kk < GBK; kk += 16) {
            uint32_t ahi[2][4], alo[2][4], bhi[4][2], blo[4][2];
            int kc = kk + tg * 2;
#pragma unroll
            for (int mt = 0; mt < 2; mt++) {
                int r = wm0 + mt * 16 + g;
                ahi[mt][0] = lds32(sAhi, r,     kc);
                ahi[mt][1] = lds32(sAhi, r + 8, kc);
                ahi[mt][2] = lds32(sAhi, r,     kc + 8);
                ahi[mt][3] = lds32(sAhi, r + 8, kc + 8);
                alo[mt][0] = lds32(sAlo, r,     kc);
                alo[mt][1] = lds32(sAlo, r + 8, kc);
                alo[mt][2] = lds32(sAlo, r,     kc + 8);
                alo[mt][3] = lds32(sAlo, r + 8, kc + 8);
            }
#pragma unroll
            for (int nt = 0; nt < 4; nt++) {
                int rn = wn0 + nt * 8 + g;
                bhi[nt][0] = lds32(sBhi, rn, kc);
                bhi[nt][1] = lds32(sBhi, rn, kc + 8);
                blo[nt][0] = lds32(sBlo, rn, kc);
                blo[nt][1] = lds32(sBlo, rn, kc + 8);
            }
#pragma unroll
            for (int mt = 0; mt < 2; mt++)
#pragma unroll
                for (int nt = 0; nt < 4; nt++) {
                    mma16816(acc[mt][nt], ahi[mt], bhi[nt]);
                    mma16816(acc[mt][nt], ahi[mt], blo[nt]);
                    mma16816(acc[mt][nt], alo[mt], bhi[nt]);
                }
        }
        __syncthreads();
    }

    // epilogue
#pragma unroll
    for (int mt = 0; mt < 2; mt++) {
#pragma unroll
        for (int nt = 0; nt < 4; nt++) {
            int row = m0 + wm0 + mt * 16 + g;
            int colL = wn0 + nt * 8 + tg * 2;
            int col = n0 + colL;
            float b0 = sbias[colL], b1 = sbias[colL + 1];
            if (row < N_NODES) {
                float2 o0 = make_float2(acc[mt][nt][0] + b0, acc[mt][nt][1] + b1);
                *(float2*)(out + (size_t)row * C_OUT + col) = o0;
            }
            if (row + 8 < N_NODES) {
                float2 o1 = make_float2(acc[mt][nt][2] + b0, acc[mt][nt][3] + b1);
                *(float2*)(out + (size_t)(row + 8) * C_OUT + col) = o1;
            }
        }
    }
}

// ---------------- host launch ----------------
extern "C" void kernel_launch(void* const* d_in, const int* in_sizes, int n_in,
                              void* d_out, int out_size) {
    const float* h    = (const float*)d_in[0];
    const float* X    = (const float*)d_in[1];
    const int*   ei   = (const int*)d_in[2];
    const float* W    = (const float*)d_in[4];
    const float* bias = (const float*)d_in[5];
    float* out = (float*)d_out;

    int rp_blocks = (N_EDGES + 1 + 255) / 256;   // 1251
    prep_kernel<<<WT_BLOCKS + rp_blocks, 256>>>(ei, W);
    edge_accum_kernel<<<(N_NODES * 32 + 255) / 256, 256>>>(h, X, ei);
    cudaFuncSetAttribute(gemm_hmma_kernel,
                         cudaFuncAttributeMaxDynamicSharedMemorySize, GSMEM);
    gemm_hmma_kernel<<<dim3(M_PAD / GBM, C_OUT / GBN), 128, GSMEM>>>(bias, out);
}

// round 8
// speedup vs baseline: 1.8095x; 1.0490x over previous
#include <cuda_runtime.h>
#include <cuda_bf16.h>
#include <cstdint>

#define N_NODES 10000
#define N_EDGES 320000
#define KDIM 5
#define C_IN 128
#define C_OUT 128
#define KI 640            // KDIM * C_IN
#define M_PAD 10048       // 157 * 64 (zero pad rows stay zero forever)

// ---------------- device scratch (alloc-free) ----------------
__device__ __nv_bfloat16 g_Ahi[(size_t)M_PAD * KI];
__device__ __nv_bfloat16 g_Alo[(size_t)M_PAD * KI];
__device__ __nv_bfloat16 g_Bhi[(size_t)C_OUT * KI];   // [o][ki] K-major (= B col-major)
__device__ __nv_bfloat16 g_Blo[(size_t)C_OUT * KI];
__device__ int g_rowptr[N_NODES + 1];

// ---------------- helpers ----------------
__device__ __forceinline__ unsigned long long pk2(float a, float b) {
    unsigned long long r;
    asm("mov.b64 %0, {%1, %2};" : "=l"(r) : "f"(a), "f"(b));
    return r;
}
__device__ __forceinline__ unsigned long long ffma2(unsigned long long a,
                                                    unsigned long long b,
                                                    unsigned long long c) {
    unsigned long long d;
    asm("fma.rn.f32x2 %0, %1, %2, %3;" : "=l"(d) : "l"(a), "l"(b), "l"(c));
    return d;
}
__device__ __forceinline__ void unpk2(unsigned long long v, float &a, float &b) {
    asm("mov.b64 {%0, %1}, %2;" : "=f"(a), "=f"(b) : "l"(v));
}
__device__ __forceinline__ int detect_stride(const int* __restrict__ w) {
    bool is64 = (w[N_EDGES + 1] == 0) && (w[N_EDGES + 3] == 0) &&
                (w[N_EDGES + 5] == 0) && (w[N_EDGES + 7] == 0);
    return is64 ? 2 : 1;
}
__device__ __forceinline__ uint32_t su32(const void* p) {
    return (uint32_t)__cvta_generic_to_shared(p);
}
__device__ __forceinline__ void cp16(uint32_t dst, const void* src) {
    asm volatile("cp.async.cg.shared.global [%0], [%1], 16;" :: "r"(dst), "l"(src) : "memory");
}
__device__ __forceinline__ void cp_commit() {
    asm volatile("cp.async.commit_group;" ::: "memory");
}
template <int N>
__device__ __forceinline__ void cp_wait() {
    asm volatile("cp.async.wait_group %0;" :: "n"(N) : "memory");
}
__device__ __forceinline__ void ldsm4(uint32_t& r0, uint32_t& r1, uint32_t& r2,
                                      uint32_t& r3, uint32_t saddr) {
    asm volatile("ldmatrix.sync.aligned.m8n8.x4.shared.b16 {%0,%1,%2,%3}, [%4];"
                 : "=r"(r0), "=r"(r1), "=r"(r2), "=r"(r3) : "r"(saddr));
}
// mma.sync bf16: D(f32) += A(bf16) * B(bf16), m16n8k16, A row-major, B col-major
__device__ __forceinline__ void mma16816(float* d, const uint32_t* a, const uint32_t* b) {
    asm volatile(
        "mma.sync.aligned.m16n8k16.row.col.f32.bf16.bf16.f32 "
        "{%0,%1,%2,%3}, {%4,%5,%6,%7}, {%8,%9}, {%0,%1,%2,%3};"
        : "+f"(d[0]), "+f"(d[1]), "+f"(d[2]), "+f"(d[3])
        : "r"(a[0]), "r"(a[1]), "r"(a[2]), "r"(a[3]), "r"(b[0]), "r"(b[1]));
}

// ---------------- Kernel 1: prep = W split-transpose + rowptr scatter ----------
#define WT_BLOCKS 80   // (640/32) * (128/32)
__global__ void prep_kernel(const int* __restrict__ ei, const float* __restrict__ W) {
    if (blockIdx.x < WT_BLOCKS) {
        __shared__ float tile[32][33];
        int bki = blockIdx.x >> 2;        // 0..19  (ki block)
        int bo  = blockIdx.x & 3;         // 0..3   (o block)
        int tx = threadIdx.x & 31;
        int ty = threadIdx.x >> 5;        // 0..7
#pragma unroll
        for (int j = 0; j < 4; j++) {
            int ki = bki * 32 + ty + j * 8;
            tile[ty + j * 8][tx] = W[(size_t)ki * C_OUT + bo * 32 + tx];
        }
        __syncthreads();
#pragma unroll
        for (int j = 0; j < 4; j++) {
            int o  = bo * 32 + ty + j * 8;
            int ki = bki * 32 + tx;
            float w = tile[tx][ty + j * 8];
            __nv_bfloat16 hi = __float2bfloat16(w);
            float lof = w - __bfloat162float(hi);
            g_Bhi[(size_t)o * KI + ki] = hi;
            g_Blo[(size_t)o * KI + ki] = __float2bfloat16(lof);
        }
    } else {
        int idx = (blockIdx.x - WT_BLOCKS) * 256 + threadIdx.x;
        int stride = detect_stride(ei);
        int s_cur = N_NODES;
        if (idx < N_EDGES) s_cur = ei[(size_t)idx * stride];
        int s_prev = __shfl_up_sync(0xFFFFFFFFu, s_cur, 1);
        if (idx <= N_EDGES) {
            if ((threadIdx.x & 31) == 0)
                s_prev = (idx == 0) ? -1 : ei[(size_t)(idx - 1) * stride];
            for (int n = s_prev + 1; n <= s_cur; n++) g_rowptr[n] = idx;
        }
    }
}

// ---------------- Kernel 2: per-node edge accumulation (warp per node) ---------
__global__ void __launch_bounds__(256)
edge_accum_kernel(const float* __restrict__ h,
                  const float* __restrict__ X,
                  const int* __restrict__ ei) {
    int gwarp = (blockIdx.x * blockDim.x + threadIdx.x) >> 5;
    int lane  = threadIdx.x & 31;
    if (gwarp >= N_NODES) return;

    int stride = detect_stride(ei);
    const int* dstp = ei + (size_t)N_EDGES * stride;

    int start = g_rowptr[gwarp];
    int end   = g_rowptr[gwarp + 1];

    unsigned long long acc[KDIM][2];
#pragma unroll
    for (int k = 0; k < KDIM; k++) { acc[k][0] = 0ull; acc[k][1] = 0ull; }

    const float* hb = h + lane * 4;
    int e = start;

    // unroll-4: batch independent dst + X loads, then h loads, then FMA
    for (; e + 4 <= end; e += 4) {
        int d[4];
#pragma unroll
        for (int j = 0; j < 4; j++) d[j] = dstp[(size_t)(e + j) * stride];
        float x[4][KDIM];
#pragma unroll
        for (int j = 0; j < 4; j++) {
            const float* xp = X + (size_t)(e + j) * KDIM;
#pragma unroll
            for (int k = 0; k < KDIM; k++) x[j][k] = __ldg(xp + k);
        }
        float4 hv[4];
#pragma unroll
        for (int j = 0; j < 4; j++)
            hv[j] = *(const float4*)(hb + (size_t)d[j] * C_IN);
#pragma unroll
        for (int j = 0; j < 4; j++) {
            unsigned long long h01 = pk2(hv[j].x, hv[j].y);
            unsigned long long h23 = pk2(hv[j].z, hv[j].w);
#pragma unroll
            for (int k = 0; k < KDIM; k++) {
                unsigned long long x2 = pk2(x[j][k], x[j][k]);
                acc[k][0] = ffma2(x2, h01, acc[k][0]);
                acc[k][1] = ffma2(x2, h23, acc[k][1]);
            }
        }
    }
    for (; e < end; e++) {
        int d = dstp[(size_t)e * stride];
        float4 hv = *(const float4*)(hb + (size_t)d * C_IN);
        unsigned long long h01 = pk2(hv.x, hv.y), h23 = pk2(hv.z, hv.w);
        const float* xp = X + (size_t)e * KDIM;
#pragma unroll
        for (int k = 0; k < KDIM; k++) {
            float xk = __ldg(xp + k);
            unsigned long long x2 = pk2(xk, xk);
            acc[k][0] = ffma2(x2, h01, acc[k][0]);
            acc[k][1] = ffma2(x2, h23, acc[k][1]);
        }
    }

    // emit bf16 hi/lo pairs
#pragma unroll
    for (int k = 0; k < KDIM; k++) {
        float4 v;
        unpk2(acc[k][0], v.x, v.y);
        unpk2(acc[k][1], v.z, v.w);
        size_t idx = (size_t)gwarp * KI + k * C_IN + lane * 4;
        __nv_bfloat162 h01 = __float22bfloat162_rn(make_float2(v.x, v.y));
        __nv_bfloat162 h23 = __float22bfloat162_rn(make_float2(v.z, v.w));
        float l0 = v.x - __bfloat162float(h01.x);
        float l1 = v.y - __bfloat162float(h01.y);
        float l2 = v.z - __bfloat162float(h23.x);
        float l3 = v.w - __bfloat162float(h23.y);
        __nv_bfloat162 lo01 = __float22bfloat162_rn(make_float2(l0, l1));
        __nv_bfloat162 lo23 = __float22bfloat162_rn(make_float2(l2, l3));
        uint2 hs, ls;
        hs.x = *(uint32_t*)&h01; hs.y = *(uint32_t*)&h23;
        ls.x = *(uint32_t*)&lo01; ls.y = *(uint32_t*)&lo23;
        *(uint2*)(&g_Ahi[idx]) = hs;
        *(uint2*)(&g_Alo[idx]) = ls;
    }
}

// ---------------- Kernel 3: HMMA bf16-split GEMM, 64x64 tiles, ldmatrix --------
// out(10000x128) = Ahi@Bhi^T + Ahi@Blo^T + Alo@Bhi^T + bias
#define GBM 64
#define GBN 64
#define GBK 32
#define NSTAGE 20            // KI / GBK
#define APITCH 40            // bf16 per row (80 B): ldmatrix phases hit all 32 banks
#define TILE_B (64 * APITCH * 2)         // 5120 B per tile
#define STAGE_B (4 * TILE_B)             // 20480 B
#define GSMEM (3 * STAGE_B)              // 61440 B (3-stage pipeline)

__global__ void __launch_bounds__(128, 2)
gemm_hmma_kernel(const float* __restrict__ bias, float* __restrict__ out) {
    extern __shared__ __align__(16) char smem[];
    __shared__ float sbias[GBN];

    int tid = threadIdx.x;
    int lane = tid & 31, wid = tid >> 5;
    int g = lane >> 2, tg = lane & 3;
    int m0 = blockIdx.x * GBM;
    int n0 = blockIdx.y * GBN;
    int wm0 = (wid & 1) * 32;       // warp tile 32 x 32
    int wn0 = (wid >> 1) * 32;

    if (tid < GBN) sbias[tid] = bias[n0 + tid];

    uint32_t sb = su32(smem);

    // ldmatrix per-lane byte offsets (within a tile)
    int lr = lane & 7;
    int aR = ((lane >> 3) & 1) * 8;   // mat0:+0 mat1:+8 mat2:+0 mat3:+8 (rows)
    int aC = (lane >> 4) * 8;         // mat0,1:+0 mat2,3:+8 (k)
    int bR = (lane >> 4) * 8;         // B: mats 2,3 take next n-8 block
    int bC = ((lane >> 3) & 1) * 8;   // B: mats 1,3 take k+8
    uint32_t offA0 = (uint32_t)(((wm0 +  0 + lr + aR) * APITCH + aC) * 2);
    uint32_t offA1 = (uint32_t)(((wm0 + 16 + lr + aR) * APITCH + aC) * 2);
    uint32_t offB0 = (uint32_t)(((wn0 +  0 + lr + bR) * APITCH + bC) * 2);
    uint32_t offB1 = (uint32_t)(((wn0 + 16 + lr + bR) * APITCH + bC) * 2);

    // stage loader: 4 tiles x 256 16B-words, 2 cp16 per thread per tile
    int sstage = 0;   // smem stage slot for load_stage (explicit wrap, no div)
    auto load_stage = [&](int i) {
        int k0 = i * GBK;
        char* sbuf = smem + sstage * STAGE_B;
        if (++sstage == 3) sstage = 0;
        const __nv_bfloat16* srcs[4] = {
            g_Ahi + (size_t)m0 * KI + k0,
            g_Alo + (size_t)m0 * KI + k0,
            g_Bhi + (size_t)n0 * KI + k0,
            g_Blo + (size_t)n0 * KI + k0 };
#pragma unroll
        for (int t = 0; t < 4; t++) {
            uint32_t dbase = su32(sbuf + t * TILE_B);
            const __nv_bfloat16* src = srcs[t];
#pragma unroll
            for (int j = 0; j < 2; j++) {
                int w = tid + j * 128;          // 0..255
                int r = w >> 2, c = w & 3;
                cp16(dbase + (uint32_t)(r * (APITCH * 2) + c * 16),
                     src + (size_t)r * KI + c * 8);
            }
        }
        cp_commit();
    };

    float acc[2][4][4];
#pragma unroll
    for (int mt = 0; mt < 2; mt++)
#pragma unroll
        for (int nt = 0; nt < 4; nt++)
#pragma unroll
            for (int j = 0; j < 4; j++) acc[mt][nt][j] = 0.0f;

    load_stage(0);
    load_stage(1);

    int cstage = 0;   // compute stage slot
    for (int i = 0; i < NSTAGE; i++) {
        if (i + 2 < NSTAGE)      { load_stage(i + 2); cp_wait<2>(); }
        else if (i + 1 < NSTAGE) { cp_wait<1>(); }
        else                     { cp_wait<0>(); }
        __syncthreads();

        uint32_t base = sb + (uint32_t)(cstage * STAGE_B);
        if (++cstage == 3) cstage = 0;
        uint32_t bAhi = base;
        uint32_t bAlo = base + TILE_B;
        uint32_t bBhi = base + 2 * TILE_B;
        uint32_t bBlo = base + 3 * TILE_B;

#pragma unroll
        for (int kk = 0; kk < GBK; kk += 16) {
            uint32_t ko = (uint32_t)(kk * 2);
            uint32_t ahi[2][4], alo[2][4], bhi[4][2], blo[4][2];
            ldsm4(ahi[0][0], ahi[0][1], ahi[0][2], ahi[0][3], bAhi + offA0 + ko);
            ldsm4(ahi[1][0], ahi[1][1], ahi[1][2], ahi[1][3], bAhi + offA1 + ko);
            ldsm4(alo[0][0], alo[0][1], alo[0][2], alo[0][3], bAlo + offA0 + ko);
            ldsm4(alo[1][0], alo[1][1], alo[1][2], alo[1][3], bAlo + offA1 + ko);
            ldsm4(bhi[0][0], bhi[0][1], bhi[1][0], bhi[1][1], bBhi + offB0 + ko);
            ldsm4(bhi[2][0], bhi[2][1], bhi[3][0], bhi[3][1], bBhi + offB1 + ko);
            ldsm4(blo[0][0], blo[0][1], blo[1][0], blo[1][1], bBlo + offB0 + ko);
            ldsm4(blo[2][0], blo[2][1], blo[3][0], blo[3][1], bBlo + offB1 + ko);
#pragma unroll
            for (int mt = 0; mt < 2; mt++)
#pragma unroll
                for (int nt = 0; nt < 4; nt++) {
                    mma16816(acc[mt][nt], ahi[mt], bhi[nt]);
                    mma16816(acc[mt][nt], ahi[mt], blo[nt]);
                    mma16816(acc[mt][nt], alo[mt], bhi[nt]);
                }
        }
        __syncthreads();
    }

    // epilogue
#pragma unroll
    for (int mt = 0; mt < 2; mt++) {
#pragma unroll
        for (int nt = 0; nt < 4; nt++) {
            int row = m0 + wm0 + mt * 16 + g;
            int colL = wn0 + nt * 8 + tg * 2;
            int col = n0 + colL;
            float b0 = sbias[colL], b1 = sbias[colL + 1];
            if (row < N_NODES) {
                float2 o0 = make_float2(acc[mt][nt][0] + b0, acc[mt][nt][1] + b1);
                *(float2*)(out + (size_t)row * C_OUT + col) = o0;
            }
            if (row + 8 < N_NODES) {
                float2 o1 = make_float2(acc[mt][nt][2] + b0, acc[mt][nt][3] + b1);
                *(float2*)(out + (size_t)(row + 8) * C_OUT + col) = o1;
            }
        }
    }
}

// ---------------- host launch ----------------
extern "C" void kernel_launch(void* const* d_in, const int* in_sizes, int n_in,
                              void* d_out, int out_size) {
    const float* h    = (const float*)d_in[0];
    const float* X    = (const float*)d_in[1];
    const int*   ei   = (const int*)d_in[2];
    const float* W    = (const float*)d_in[4];
    const float* bias = (const float*)d_in[5];
    float* out = (float*)d_out;

    int rp_blocks = (N_EDGES + 1 + 255) / 256;   // 1251
    prep_kernel<<<WT_BLOCKS + rp_blocks, 256>>>(ei, W);
    edge_accum_kernel<<<(N_NODES * 32 + 255) / 256, 256>>>(h, X, ei);
    cudaFuncSetAttribute(gemm_hmma_kernel,
                         cudaFuncAttributeMaxDynamicSharedMemorySize, GSMEM);
    gemm_hmma_kernel<<<dim3(M_PAD / GBM, C_OUT / GBN), 128, GSMEM>>>(bias, out);
}